// round 4
// baseline (speedup 1.0000x reference)
#include <cuda_runtime.h>
#include <math.h>

// ---------------- problem constants ----------------
#define BATCH   4
#define NTOK    1025
#define DMODEL  768
#define NHEAD   8
#define DHEAD   64
#define QKVD    1536          // 3*H*DH = 3*8*64  (NOT 3*D!)
#define HD      512           // H*DH
#define MLPD    2048
#define NPATCH  1024
#define ROWS    (BATCH*NTOK)  // 4100
#define DEPTH   12

// ---------------- scratch (device globals; no allocation allowed) ----------------
__device__ __align__(16) float g_t[BATCH*NTOK*DMODEL];        // residual stream
__device__ __align__(16) float g_h[BATCH*NTOK*DMODEL];        // LN output
__device__ __align__(16) float g_qkv[BATCH*NTOK*QKVD];
__device__ __align__(16) float g_o[BATCH*NTOK*HD];
__device__ __align__(16) float g_ffn[BATCH*NTOK*MLPD];
__device__ __align__(16) float g_patches[4096*256];
__device__ __align__(16) float g_tok[4096*DMODEL];
__device__ __align__(16) float g_wT[256*DMODEL];

// ---------------- helpers ----------------
__device__ __forceinline__ float gelu_exact(float x) {
    return 0.5f * x * (1.0f + erff(x * 0.70710678118654752f));
}

// ---------------- im2col: extract 16x16 patches (C=1) ----------------
__global__ void im2col_kernel(const float* __restrict__ x) {
    int idx = blockIdx.x * blockDim.x + threadIdx.x;
    if (idx >= 4096*256) return;
    int k   = idx & 255;          // p*16+q
    int row = idx >> 8;           // b*1024 + gy*32 + gx
    int b   = row >> 10;
    int pr  = row & 1023;
    int gy  = pr >> 5, gx = pr & 31;
    int p   = k >> 4,  q  = k & 15;
    g_patches[idx] = x[((size_t)(b*512 + gy*16 + p))*512 + gx*16 + q];
}

// ---------------- transpose conv_w [768,256] -> wT [256,768] ----------------
__global__ void wtrans_kernel(const float* __restrict__ w) {
    int idx = blockIdx.x * blockDim.x + threadIdx.x;
    if (idx >= 768*256) return;
    int d = idx >> 8, k = idx & 255;
    g_wT[k*DMODEL + d] = w[idx];
}

// ---------------- assemble t = concat(cls, tok) + pos ----------------
__global__ void assemble_kernel(const float* __restrict__ cls,
                                const float* __restrict__ pos) {
    int idx = blockIdx.x * blockDim.x + threadIdx.x;
    if (idx >= ROWS*DMODEL) return;
    int d = idx % DMODEL;
    int n = (idx / DMODEL) % NTOK;
    int b = idx / (DMODEL*NTOK);
    float v;
    if (n == 0) v = cls[d];
    else        v = g_tok[((size_t)(b*NPATCH + n - 1))*DMODEL + d];
    g_t[idx] = v + pos[n*DMODEL + d];
}

// ---------------- LayerNorm: one block per row of 768 ----------------
__global__ void ln_kernel(const float* __restrict__ x, const float* __restrict__ sc,
                          const float* __restrict__ bi, float* __restrict__ y) {
    int row = blockIdx.x;
    const float* xr = x + (size_t)row * DMODEL;
    float*       yr = y + (size_t)row * DMODEL;
    int tid = threadIdx.x;
    float v0 = xr[tid], v1 = xr[tid+256], v2 = xr[tid+512];
    float s1 = v0 + v1 + v2;
    float s2 = v0*v0 + v1*v1 + v2*v2;
    #pragma unroll
    for (int o = 16; o; o >>= 1) {
        s1 += __shfl_xor_sync(0xffffffffu, s1, o);
        s2 += __shfl_xor_sync(0xffffffffu, s2, o);
    }
    __shared__ float r1[8], r2[8];
    if ((tid & 31) == 0) { r1[tid>>5] = s1; r2[tid>>5] = s2; }
    __syncthreads();
    float t1 = 0.f, t2 = 0.f;
    #pragma unroll
    for (int w = 0; w < 8; w++) { t1 += r1[w]; t2 += r2[w]; }
    float mean = t1 * (1.0f/768.0f);
    float var  = t2 * (1.0f/768.0f) - mean*mean;
    float rstd = rsqrtf(var + 1e-5f);
    yr[tid]     = (v0-mean)*rstd*sc[tid]     + bi[tid];
    yr[tid+256] = (v1-mean)*rstd*sc[tid+256] + bi[tid+256];
    yr[tid+512] = (v2-mean)*rstd*sc[tid+512] + bi[tid+512];
}

// ---------------- SGEMM: C[M,Nn] = act(A[M,K] @ B[K,Nn] + bias) + res ----------------
// BM=128 BN=64 BK=16, 256 threads, 8x4 register tile.
#define BM 128
#define BN 64
#define BK 16
#define TM 8
#define TN 4
__global__ void __launch_bounds__(256, 2)
gemm_kernel(const float* __restrict__ A, const float* __restrict__ Bm,
            const float* __restrict__ bias, const float* __restrict__ res,
            float* __restrict__ C, int M, int K, int Nn, int act) {
    __shared__ float Ast[BK][BM + 4];   // A tile stored transposed (k-major)
    __shared__ float Bs[BK][BN];
    int tid = threadIdx.x;
    int tx = tid & 15, ty = tid >> 4;
    int bm = blockIdx.y * BM, bn = blockIdx.x * BN;

    float acc[TM][TN];
    #pragma unroll
    for (int i = 0; i < TM; i++)
        #pragma unroll
        for (int j = 0; j < TN; j++) acc[i][j] = 0.f;

    for (int k0 = 0; k0 < K; k0 += BK) {
        // A tile: 128x16 = 512 float4; 2 per thread
        #pragma unroll
        for (int l = 0; l < 2; l++) {
            int idx = tid + l*256;
            int r = idx >> 2, c4 = (idx & 3) * 4;
            int gr = bm + r;
            float4 v = make_float4(0.f,0.f,0.f,0.f);
            if (gr < M) v = *(const float4*)&A[(size_t)gr*K + k0 + c4];
            Ast[c4+0][r] = v.x; Ast[c4+1][r] = v.y;
            Ast[c4+2][r] = v.z; Ast[c4+3][r] = v.w;
        }
        // B tile: 16x64 = 256 float4; 1 per thread
        {
            int r = tid >> 4, c4 = (tid & 15) * 4;
            *(float4*)&Bs[r][c4] = *(const float4*)&Bm[(size_t)(k0 + r)*Nn + bn + c4];
        }
        __syncthreads();
        #pragma unroll
        for (int k = 0; k < BK; k++) {
            float4 b4 = *(float4*)&Bs[k][tx*4];
            float4 a0 = *(float4*)&Ast[k][ty*TM];
            float4 a1 = *(float4*)&Ast[k][ty*TM + 4];
            float af[TM] = {a0.x,a0.y,a0.z,a0.w,a1.x,a1.y,a1.z,a1.w};
            #pragma unroll
            for (int i = 0; i < TM; i++) {
                acc[i][0] += af[i]*b4.x; acc[i][1] += af[i]*b4.y;
                acc[i][2] += af[i]*b4.z; acc[i][3] += af[i]*b4.w;
            }
        }
        __syncthreads();
    }

    int cn = bn + tx*4;
    float4 bi = make_float4(0.f,0.f,0.f,0.f);
    if (bias) bi = *(const float4*)&bias[cn];
    #pragma unroll
    for (int i = 0; i < TM; i++) {
        int gr = bm + ty*TM + i;
        if (gr >= M) continue;
        float4 v;
        v.x = acc[i][0]+bi.x; v.y = acc[i][1]+bi.y;
        v.z = acc[i][2]+bi.z; v.w = acc[i][3]+bi.w;
        if (act == 1) {
            v.x = gelu_exact(v.x); v.y = gelu_exact(v.y);
            v.z = gelu_exact(v.z); v.w = gelu_exact(v.w);
        }
        if (res) {
            float4 r4 = *(const float4*)&res[(size_t)gr*Nn + cn];
            v.x += r4.x; v.y += r4.y; v.z += r4.z; v.w += r4.w;
        }
        *(float4*)&C[(size_t)gr*Nn + cn] = v;
    }
}

// ---------------- flash-style attention ----------------
// grid (17 qtiles, 8 heads, 4 batch), 256 threads, 64-query tile.
// smem: Qs / Ks(->Ps) / Vs, pitch 68 floats each (bank-conflict pad, float4-aligned).
#define APITCH 68
#define ATTN_SMEM (3*64*APITCH*4)
__global__ void attn_kernel(const float* __restrict__ qkv, float* __restrict__ o) {
    extern __shared__ float sm[];
    float* Qs = sm;
    float* Ks = sm + 64*APITCH;   // reused as Ps after S is computed
    float* Vs = sm + 2*64*APITCH;

    int tid = threadIdx.x;
    int qt = blockIdx.x, h = blockIdx.y, b = blockIdx.z;
    int tr = tid >> 4, tc = tid & 15;

    // load Q tile (zero-pad invalid rows)
    #pragma unroll
    for (int it = 0; it < 4; it++) {
        int r  = (tid >> 4) + it*16;
        int c4 = (tid & 15) * 4;
        int qn = qt*64 + r;
        float4 qv = make_float4(0.f,0.f,0.f,0.f);
        if (qn < NTOK)
            qv = *(const float4*)(qkv + ((size_t)(b*NTOK + qn))*QKVD + h*192 + c4);
        *(float4*)&Qs[r*APITCH + c4] = qv;
    }

    float m[4], l[4], oacc[4][4];
    #pragma unroll
    for (int i = 0; i < 4; i++) {
        m[i] = -1e30f; l[i] = 0.f;
        #pragma unroll
        for (int j = 0; j < 4; j++) oacc[i][j] = 0.f;
    }

    for (int kt = 0; kt < 17; kt++) {
        __syncthreads();   // prev iter consumers of Ks/Vs done
        #pragma unroll
        for (int it = 0; it < 4; it++) {
            int r  = (tid >> 4) + it*16;
            int c4 = (tid & 15) * 4;
            int kn = kt*64 + r;
            float4 kv = make_float4(0.f,0.f,0.f,0.f);
            float4 vv = make_float4(0.f,0.f,0.f,0.f);
            if (kn < NTOK) {
                const float* base = qkv + ((size_t)(b*NTOK + kn))*QKVD + h*192;
                kv = *(const float4*)(base + 64  + c4);
                vv = *(const float4*)(base + 128 + c4);
            }
            *(float4*)&Ks[r*APITCH + c4] = kv;
            *(float4*)&Vs[r*APITCH + c4] = vv;
        }
        __syncthreads();

        // S = Q K^T for this thread's 4x4 tile
        float s[4][4];
        #pragma unroll
        for (int i = 0; i < 4; i++)
            #pragma unroll
            for (int j = 0; j < 4; j++) s[i][j] = 0.f;
        #pragma unroll 4
        for (int d = 0; d < 64; d += 4) {
            float4 q[4], k[4];
            #pragma unroll
            for (int i = 0; i < 4; i++) q[i] = *(float4*)&Qs[(4*tr+i)*APITCH + d];
            #pragma unroll
            for (int j = 0; j < 4; j++) k[j] = *(float4*)&Ks[(4*tc+j)*APITCH + d];
            #pragma unroll
            for (int i = 0; i < 4; i++)
                #pragma unroll
                for (int j = 0; j < 4; j++) {
                    s[i][j] += q[i].x*k[j].x;
                    s[i][j] += q[i].y*k[j].y;
                    s[i][j] += q[i].z*k[j].z;
                    s[i][j] += q[i].w*k[j].w;
                }
        }

        // scale + mask + online softmax update
        #pragma unroll
        for (int i = 0; i < 4; i++) {
            float tmax = -1e30f;
            #pragma unroll
            for (int j = 0; j < 4; j++) {
                int kn = kt*64 + 4*tc + j;
                s[i][j] = (kn < NTOK) ? s[i][j]*0.125f : -1e30f;
                tmax = fmaxf(tmax, s[i][j]);
            }
            #pragma unroll
            for (int off = 8; off; off >>= 1)
                tmax = fmaxf(tmax, __shfl_xor_sync(0xffffffffu, tmax, off));
            float mn = fmaxf(m[i], tmax);
            float alpha = expf(m[i] - mn);
            m[i] = mn;
            float rs = 0.f;
            #pragma unroll
            for (int j = 0; j < 4; j++) { s[i][j] = expf(s[i][j] - mn); rs += s[i][j]; }
            #pragma unroll
            for (int off = 8; off; off >>= 1)
                rs += __shfl_xor_sync(0xffffffffu, rs, off);
            l[i] = l[i]*alpha + rs;
            #pragma unroll
            for (int j = 0; j < 4; j++) oacc[i][j] *= alpha;
        }

        __syncthreads();   // everyone done reading Ks
        #pragma unroll
        for (int i = 0; i < 4; i++)
            #pragma unroll
            for (int j = 0; j < 4; j++)
                Ks[(4*tr+i)*APITCH + 4*tc + j] = s[i][j];   // P tile
        __syncthreads();

        // O += P @ V
        #pragma unroll 4
        for (int c = 0; c < 64; c++) {
            float4 v4 = *(float4*)&Vs[c*APITCH + 4*tc];
            #pragma unroll
            for (int i = 0; i < 4; i++) {
                float p = Ks[(4*tr+i)*APITCH + c];
                oacc[i][0] += p*v4.x; oacc[i][1] += p*v4.y;
                oacc[i][2] += p*v4.z; oacc[i][3] += p*v4.w;
            }
        }
    }

    #pragma unroll
    for (int i = 0; i < 4; i++) {
        int n = qt*64 + 4*tr + i;
        if (n < NTOK) {
            float inv = 1.0f / l[i];
            float4 v;
            v.x = oacc[i][0]*inv; v.y = oacc[i][1]*inv;
            v.z = oacc[i][2]*inv; v.w = oacc[i][3]*inv;
            *(float4*)(o + ((size_t)(b*NTOK + n))*HD + h*64 + 4*tc) = v;
        }
    }
}

// ---------------- driver ----------------
extern "C" void kernel_launch(void* const* d_in, const int* in_sizes, int n_in,
                              void* d_out, int out_size) {
    const float* x       = (const float*)d_in[0];
    const float* conv_w  = (const float*)d_in[1];
    const float* conv_b  = (const float*)d_in[2];
    const float* cls     = (const float*)d_in[3];
    const float* pos     = (const float*)d_in[4];
    const float* qkv_w   = (const float*)d_in[5];
    const float* merge_w = (const float*)d_in[6];
    const float* merge_b = (const float*)d_in[7];
    const float* ln1_s   = (const float*)d_in[8];
    const float* ln1_b   = (const float*)d_in[9];
    const float* ln2_s   = (const float*)d_in[10];
    const float* ln2_b   = (const float*)d_in[11];
    const float* ffn_w1  = (const float*)d_in[12];
    const float* ffn_b1  = (const float*)d_in[13];
    const float* ffn_w2  = (const float*)d_in[14];
    const float* ffn_b2  = (const float*)d_in[15];
    const float* lnf_s   = (const float*)d_in[16];
    const float* lnf_b   = (const float*)d_in[17];
    float* out = (float*)d_out;

    float *t_p, *h_p, *qkv_p, *o_p, *ffn_p, *patches_p, *tok_p, *wT_p;
    cudaGetSymbolAddress((void**)&t_p,       g_t);
    cudaGetSymbolAddress((void**)&h_p,       g_h);
    cudaGetSymbolAddress((void**)&qkv_p,     g_qkv);
    cudaGetSymbolAddress((void**)&o_p,       g_o);
    cudaGetSymbolAddress((void**)&ffn_p,     g_ffn);
    cudaGetSymbolAddress((void**)&patches_p, g_patches);
    cudaGetSymbolAddress((void**)&tok_p,     g_tok);
    cudaGetSymbolAddress((void**)&wT_p,      g_wT);

    cudaFuncSetAttribute(attn_kernel, cudaFuncAttributeMaxDynamicSharedMemorySize,
                         ATTN_SMEM);

    const int MB = (ROWS + BM - 1) / BM;   // 33

    // patch embedding
    im2col_kernel<<<4096, 256>>>(x);
    wtrans_kernel<<<768, 256>>>(conv_w);
    gemm_kernel<<<dim3(DMODEL/BN, 4096/BM), 256>>>(
        patches_p, wT_p, conv_b, nullptr, tok_p, 4096, 256, DMODEL, 0);
    assemble_kernel<<<(ROWS*DMODEL + 255)/256, 256>>>(cls, pos);

    for (int i = 0; i < DEPTH; i++) {
        ln_kernel<<<ROWS, 256>>>(t_p, ln1_s + i*DMODEL, ln1_b + i*DMODEL, h_p);
        gemm_kernel<<<dim3(QKVD/BN, MB), 256>>>(
            h_p, qkv_w + (size_t)i*DMODEL*QKVD, nullptr, nullptr,
            qkv_p, ROWS, DMODEL, QKVD, 0);
        attn_kernel<<<dim3(17, NHEAD, BATCH), 256, ATTN_SMEM>>>(qkv_p, o_p);
        gemm_kernel<<<dim3(DMODEL/BN, MB), 256>>>(
            o_p, merge_w + (size_t)i*HD*DMODEL, merge_b + i*DMODEL, t_p,
            t_p, ROWS, HD, DMODEL, 0);
        ln_kernel<<<ROWS, 256>>>(t_p, ln2_s + i*DMODEL, ln2_b + i*DMODEL, h_p);
        gemm_kernel<<<dim3(MLPD/BN, MB), 256>>>(
            h_p, ffn_w1 + (size_t)i*DMODEL*MLPD, ffn_b1 + i*MLPD, nullptr,
            ffn_p, ROWS, DMODEL, MLPD, 1);
        gemm_kernel<<<dim3(DMODEL/BN, MB), 256>>>(
            ffn_p, ffn_w2 + (size_t)i*MLPD*DMODEL, ffn_b2 + i*DMODEL, t_p,
            t_p, ROWS, MLPD, DMODEL, 0);
    }
    ln_kernel<<<ROWS, 256>>>(t_p, lnf_s, lnf_b, out);
}

// round 7
// speedup vs baseline: 1.6885x; 1.6885x over previous
#include <cuda_runtime.h>
#include <math.h>
#include <stdint.h>

// ---------------- problem constants ----------------
#define BATCH   4
#define NTOK    1025
#define DMODEL  768
#define NHEAD   8
#define DHEAD   64
#define QKVD    1536          // 3*H*DH = 3*8*64
#define HD      512           // H*DH
#define MLPD    2048
#define NPATCH  1024
#define ROWS    (BATCH*NTOK)  // 4100
#define DEPTH   12

// ---------------- scratch (device globals; no allocation allowed) ----------------
__device__ __align__(16) float g_t[BATCH*NTOK*DMODEL];        // residual stream
__device__ __align__(16) float g_h[BATCH*NTOK*DMODEL];        // LN output
__device__ __align__(16) float g_qkv[BATCH*NTOK*QKVD];
__device__ __align__(16) float g_o[BATCH*NTOK*HD];
__device__ __align__(16) float g_ffn[BATCH*NTOK*MLPD];
__device__ __align__(16) float g_patches[4096*256];
__device__ __align__(16) float g_tok[4096*DMODEL];
__device__ __align__(16) float g_wT[256*DMODEL];

// ---------------- helpers ----------------
__device__ __forceinline__ float gelu_exact(float x) {
    return 0.5f * x * (1.0f + erff(x * 0.70710678118654752f));
}
__device__ __forceinline__ float tf32r(float x) {
    uint32_t u;
    asm("cvt.rna.tf32.f32 %0, %1;" : "=r"(u) : "f"(x));
    return __uint_as_float(u);
}

// ---------------- im2col: extract 16x16 patches (C=1) ----------------
__global__ void im2col_kernel(const float* __restrict__ x) {
    int idx = blockIdx.x * blockDim.x + threadIdx.x;
    if (idx >= 4096*256) return;
    int k   = idx & 255;
    int row = idx >> 8;
    int b   = row >> 10;
    int pr  = row & 1023;
    int gy  = pr >> 5, gx = pr & 31;
    int p   = k >> 4,  q  = k & 15;
    g_patches[idx] = x[((size_t)(b*512 + gy*16 + p))*512 + gx*16 + q];
}

// ---------------- transpose conv_w [768,256] -> wT [256,768] ----------------
__global__ void wtrans_kernel(const float* __restrict__ w) {
    int idx = blockIdx.x * blockDim.x + threadIdx.x;
    if (idx >= 768*256) return;
    int d = idx >> 8, k = idx & 255;
    g_wT[k*DMODEL + d] = w[idx];
}

// ---------------- assemble t = concat(cls, tok) + pos ----------------
__global__ void assemble_kernel(const float* __restrict__ cls,
                                const float* __restrict__ pos) {
    int idx = blockIdx.x * blockDim.x + threadIdx.x;
    if (idx >= ROWS*DMODEL) return;
    int d = idx % DMODEL;
    int n = (idx / DMODEL) % NTOK;
    int b = idx / (DMODEL*NTOK);
    float v;
    if (n == 0) v = cls[d];
    else        v = g_tok[((size_t)(b*NPATCH + n - 1))*DMODEL + d];
    g_t[idx] = v + pos[n*DMODEL + d];
}

// ---------------- LayerNorm: one block per row of 768 ----------------
__global__ void ln_kernel(const float* __restrict__ x, const float* __restrict__ sc,
                          const float* __restrict__ bi, float* __restrict__ y) {
    int row = blockIdx.x;
    const float* xr = x + (size_t)row * DMODEL;
    float*       yr = y + (size_t)row * DMODEL;
    int tid = threadIdx.x;
    float v0 = xr[tid], v1 = xr[tid+256], v2 = xr[tid+512];
    float s1 = v0 + v1 + v2;
    float s2 = v0*v0 + v1*v1 + v2*v2;
    #pragma unroll
    for (int o = 16; o; o >>= 1) {
        s1 += __shfl_xor_sync(0xffffffffu, s1, o);
        s2 += __shfl_xor_sync(0xffffffffu, s2, o);
    }
    __shared__ float r1[8], r2[8];
    if ((tid & 31) == 0) { r1[tid>>5] = s1; r2[tid>>5] = s2; }
    __syncthreads();
    float t1 = 0.f, t2 = 0.f;
    #pragma unroll
    for (int w = 0; w < 8; w++) { t1 += r1[w]; t2 += r2[w]; }
    float mean = t1 * (1.0f/768.0f);
    float var  = t2 * (1.0f/768.0f) - mean*mean;
    float rstd = rsqrtf(var + 1e-5f);
    yr[tid]     = (v0-mean)*rstd*sc[tid]     + bi[tid];
    yr[tid+256] = (v1-mean)*rstd*sc[tid+256] + bi[tid+256];
    yr[tid+512] = (v2-mean)*rstd*sc[tid+512] + bi[tid+512];
}

// ---------------- TF32 tensor-core GEMM ----------------
// C[M,Nn] = act(A[M,K] @ B[K,Nn] + bias) + res
// BM=128 BN=128 BK=16, 256 threads, 8 warps as 4(M)x2(N); warp tile 32x64.
// mma.sync.aligned.m16n8k8.row.col.f32.tf32.tf32.f32
#define BM 128
#define BN 128
#define BK 16
#define APAD 20    // A smem pitch (floats): 20 mod 32 -> conflict-free frag loads
#define BPAD 136   // B smem pitch (floats): 136 mod 32 = 8 -> conflict-free

__global__ void __launch_bounds__(256)
gemm_tf32_kernel(const float* __restrict__ A, const float* __restrict__ Bm,
                 const float* __restrict__ bias, const float* __restrict__ res,
                 float* __restrict__ C, int M, int K, int Nn, int act) {
    __shared__ float As[2][BM][APAD];
    __shared__ float Bs[2][BK][BPAD];

    int tid  = threadIdx.x;
    int warp = tid >> 5, lane = tid & 31;
    int g = lane >> 2, t = lane & 3;
    int wm = (warp >> 1) * 32;   // warp M offset within block: 0,32,64,96
    int wn = (warp & 1) * 64;    // warp N offset within block: 0,64
    int bm = blockIdx.y * BM, bn = blockIdx.x * BN;

    // A-tile load mapping: 512 float4 (128 rows x 4 col-groups), 2 per thread
    int ar[2], ac[2];
    // B-tile load mapping: 512 float4 (16 rows x 32 col-groups), 2 per thread
    int br[2], bc[2];
    #pragma unroll
    for (int l = 0; l < 2; l++) {
        int idx = tid + l*256;
        ar[l] = idx >> 2;  ac[l] = (idx & 3) * 4;
        br[l] = idx >> 5;  bc[l] = (idx & 31) * 4;
    }

    float acc[2][8][4];
    #pragma unroll
    for (int mt = 0; mt < 2; mt++)
        #pragma unroll
        for (int nt = 0; nt < 8; nt++)
            #pragma unroll
            for (int j = 0; j < 4; j++) acc[mt][nt][j] = 0.f;

    int ntiles = K / BK;

    // prologue: load tile 0 into buffer 0
    #pragma unroll
    for (int l = 0; l < 2; l++) {
        int grow = bm + ar[l];
        float4 v = make_float4(0.f,0.f,0.f,0.f);
        if (grow < M) v = *(const float4*)&A[(size_t)grow*K + ac[l]];
        As[0][ar[l]][ac[l]+0] = tf32r(v.x);
        As[0][ar[l]][ac[l]+1] = tf32r(v.y);
        As[0][ar[l]][ac[l]+2] = tf32r(v.z);
        As[0][ar[l]][ac[l]+3] = tf32r(v.w);
        float4 w = *(const float4*)&Bm[(size_t)br[l]*Nn + bn + bc[l]];
        Bs[0][br[l]][bc[l]+0] = tf32r(w.x);
        Bs[0][br[l]][bc[l]+1] = tf32r(w.y);
        Bs[0][br[l]][bc[l]+2] = tf32r(w.z);
        Bs[0][br[l]][bc[l]+3] = tf32r(w.w);
    }
    __syncthreads();

    int buf = 0;
    for (int kt = 0; kt < ntiles; kt++) {
        // prefetch next tile into registers
        float4 pa[2], pb[2];
        bool has = (kt + 1) < ntiles;
        if (has) {
            int k0n = (kt + 1) * BK;
            #pragma unroll
            for (int l = 0; l < 2; l++) {
                int grow = bm + ar[l];
                pa[l] = make_float4(0.f,0.f,0.f,0.f);
                if (grow < M) pa[l] = *(const float4*)&A[(size_t)grow*K + k0n + ac[l]];
                pb[l] = *(const float4*)&Bm[(size_t)(k0n + br[l])*Nn + bn + bc[l]];
            }
        }

        // compute on smem[buf]
        #pragma unroll
        for (int ks = 0; ks < BK; ks += 8) {
            uint32_t af[2][4], bf[8][2];
            #pragma unroll
            for (int mt = 0; mt < 2; mt++) {
                int r0 = wm + mt*16 + g;
                af[mt][0] = __float_as_uint(As[buf][r0    ][ks + t    ]);
                af[mt][1] = __float_as_uint(As[buf][r0 + 8][ks + t    ]);
                af[mt][2] = __float_as_uint(As[buf][r0    ][ks + t + 4]);
                af[mt][3] = __float_as_uint(As[buf][r0 + 8][ks + t + 4]);
            }
            #pragma unroll
            for (int nt = 0; nt < 8; nt++) {
                int cn = wn + nt*8 + g;
                bf[nt][0] = __float_as_uint(Bs[buf][ks + t    ][cn]);
                bf[nt][1] = __float_as_uint(Bs[buf][ks + t + 4][cn]);
            }
            #pragma unroll
            for (int mt = 0; mt < 2; mt++)
                #pragma unroll
                for (int nt = 0; nt < 8; nt++) {
                    asm volatile(
                        "mma.sync.aligned.m16n8k8.row.col.f32.tf32.tf32.f32 "
                        "{%0,%1,%2,%3}, {%4,%5,%6,%7}, {%8,%9}, {%0,%1,%2,%3};"
                        : "+f"(acc[mt][nt][0]), "+f"(acc[mt][nt][1]),
                          "+f"(acc[mt][nt][2]), "+f"(acc[mt][nt][3])
                        : "r"(af[mt][0]), "r"(af[mt][1]), "r"(af[mt][2]), "r"(af[mt][3]),
                          "r"(bf[nt][0]), "r"(bf[nt][1]));
                }
        }

        if (has) {
            int nb = buf ^ 1;
            #pragma unroll
            for (int l = 0; l < 2; l++) {
                As[nb][ar[l]][ac[l]+0] = tf32r(pa[l].x);
                As[nb][ar[l]][ac[l]+1] = tf32r(pa[l].y);
                As[nb][ar[l]][ac[l]+2] = tf32r(pa[l].z);
                As[nb][ar[l]][ac[l]+3] = tf32r(pa[l].w);
                Bs[nb][br[l]][bc[l]+0] = tf32r(pb[l].x);
                Bs[nb][br[l]][bc[l]+1] = tf32r(pb[l].y);
                Bs[nb][br[l]][bc[l]+2] = tf32r(pb[l].z);
                Bs[nb][br[l]][bc[l]+3] = tf32r(pb[l].w);
            }
        }
        __syncthreads();
        buf ^= 1;
    }

    // epilogue: bias -> (gelu) -> (+res) -> store
    #pragma unroll
    for (int nt = 0; nt < 8; nt++) {
        int col = bn + wn + nt*8 + 2*t;
        float2 bi2 = make_float2(0.f, 0.f);
        if (bias) bi2 = *(const float2*)&bias[col];
        #pragma unroll
        for (int mt = 0; mt < 2; mt++) {
            int r0 = bm + wm + mt*16 + g;
            #pragma unroll
            for (int half = 0; half < 2; half++) {
                int row = r0 + half*8;
                if (row >= M) continue;
                float vx = acc[mt][nt][2*half + 0] + bi2.x;
                float vy = acc[mt][nt][2*half + 1] + bi2.y;
                if (act == 1) { vx = gelu_exact(vx); vy = gelu_exact(vy); }
                if (res) {
                    float2 r2 = *(const float2*)&res[(size_t)row*Nn + col];
                    vx += r2.x; vy += r2.y;
                }
                float2 o2 = make_float2(vx, vy);
                *(float2*)&C[(size_t)row*Nn + col] = o2;
            }
        }
    }
}

// ---------------- flash-style attention (fp32) ----------------
#define APITCH 68
#define ATTN_SMEM (3*64*APITCH*4)
__global__ void attn_kernel(const float* __restrict__ qkv, float* __restrict__ o) {
    extern __shared__ float sm[];
    float* Qs = sm;
    float* Ks = sm + 64*APITCH;   // reused as Ps after S is computed
    float* Vs = sm + 2*64*APITCH;

    int tid = threadIdx.x;
    int qt = blockIdx.x, h = blockIdx.y, b = blockIdx.z;
    int tr = tid >> 4, tc = tid & 15;

    #pragma unroll
    for (int it = 0; it < 4; it++) {
        int r  = (tid >> 4) + it*16;
        int c4 = (tid & 15) * 4;
        int qn = qt*64 + r;
        float4 qv = make_float4(0.f,0.f,0.f,0.f);
        if (qn < NTOK)
            qv = *(const float4*)(qkv + ((size_t)(b*NTOK + qn))*QKVD + h*192 + c4);
        *(float4*)&Qs[r*APITCH + c4] = qv;
    }

    float m[4], l[4], oacc[4][4];
    #pragma unroll
    for (int i = 0; i < 4; i++) {
        m[i] = -1e30f; l[i] = 0.f;
        #pragma unroll
        for (int j = 0; j < 4; j++) oacc[i][j] = 0.f;
    }

    for (int kt = 0; kt < 17; kt++) {
        __syncthreads();
        #pragma unroll
        for (int it = 0; it < 4; it++) {
            int r  = (tid >> 4) + it*16;
            int c4 = (tid & 15) * 4;
            int kn = kt*64 + r;
            float4 kv = make_float4(0.f,0.f,0.f,0.f);
            float4 vv = make_float4(0.f,0.f,0.f,0.f);
            if (kn < NTOK) {
                const float* base = qkv + ((size_t)(b*NTOK + kn))*QKVD + h*192;
                kv = *(const float4*)(base + 64  + c4);
                vv = *(const float4*)(base + 128 + c4);
            }
            *(float4*)&Ks[r*APITCH + c4] = kv;
            *(float4*)&Vs[r*APITCH + c4] = vv;
        }
        __syncthreads();

        float s[4][4];
        #pragma unroll
        for (int i = 0; i < 4; i++)
            #pragma unroll
            for (int j = 0; j < 4; j++) s[i][j] = 0.f;
        #pragma unroll 4
        for (int d = 0; d < 64; d += 4) {
            float4 q[4], k[4];
            #pragma unroll
            for (int i = 0; i < 4; i++) q[i] = *(float4*)&Qs[(4*tr+i)*APITCH + d];
            #pragma unroll
            for (int j = 0; j < 4; j++) k[j] = *(float4*)&Ks[(4*tc+j)*APITCH + d];
            #pragma unroll
            for (int i = 0; i < 4; i++)
                #pragma unroll
                for (int j = 0; j < 4; j++) {
                    s[i][j] += q[i].x*k[j].x;
                    s[i][j] += q[i].y*k[j].y;
                    s[i][j] += q[i].z*k[j].z;
                    s[i][j] += q[i].w*k[j].w;
                }
        }

        #pragma unroll
        for (int i = 0; i < 4; i++) {
            float tmax = -1e30f;
            #pragma unroll
            for (int j = 0; j < 4; j++) {
                int kn = kt*64 + 4*tc + j;
                s[i][j] = (kn < NTOK) ? s[i][j]*0.125f : -1e30f;
                tmax = fmaxf(tmax, s[i][j]);
            }
            #pragma unroll
            for (int off = 8; off; off >>= 1)
                tmax = fmaxf(tmax, __shfl_xor_sync(0xffffffffu, tmax, off));
            float mn = fmaxf(m[i], tmax);
            float alpha = expf(m[i] - mn);
            m[i] = mn;
            float rs = 0.f;
            #pragma unroll
            for (int j = 0; j < 4; j++) { s[i][j] = expf(s[i][j] - mn); rs += s[i][j]; }
            #pragma unroll
            for (int off = 8; off; off >>= 1)
                rs += __shfl_xor_sync(0xffffffffu, rs, off);
            l[i] = l[i]*alpha + rs;
            #pragma unroll
            for (int j = 0; j < 4; j++) oacc[i][j] *= alpha;
        }

        __syncthreads();
        #pragma unroll
        for (int i = 0; i < 4; i++)
            #pragma unroll
            for (int j = 0; j < 4; j++)
                Ks[(4*tr+i)*APITCH + 4*tc + j] = s[i][j];
        __syncthreads();

        #pragma unroll 4
        for (int c = 0; c < 64; c++) {
            float4 v4 = *(float4*)&Vs[c*APITCH + 4*tc];
            #pragma unroll
            for (int i = 0; i < 4; i++) {
                float p = Ks[(4*tr+i)*APITCH + c];
                oacc[i][0] += p*v4.x; oacc[i][1] += p*v4.y;
                oacc[i][2] += p*v4.z; oacc[i][3] += p*v4.w;
            }
        }
    }

    #pragma unroll
    for (int i = 0; i < 4; i++) {
        int n = qt*64 + 4*tr + i;
        if (n < NTOK) {
            float inv = 1.0f / l[i];
            float4 v;
            v.x = oacc[i][0]*inv; v.y = oacc[i][1]*inv;
            v.z = oacc[i][2]*inv; v.w = oacc[i][3]*inv;
            *(float4*)(o + ((size_t)(b*NTOK + n))*HD + h*64 + 4*tc) = v;
        }
    }
}

// ---------------- driver ----------------
extern "C" void kernel_launch(void* const* d_in, const int* in_sizes, int n_in,
                              void* d_out, int out_size) {
    const float* x       = (const float*)d_in[0];
    const float* conv_w  = (const float*)d_in[1];
    const float* conv_b  = (const float*)d_in[2];
    const float* cls     = (const float*)d_in[3];
    const float* pos     = (const float*)d_in[4];
    const float* qkv_w   = (const float*)d_in[5];
    const float* merge_w = (const float*)d_in[6];
    const float* merge_b = (const float*)d_in[7];
    const float* ln1_s   = (const float*)d_in[8];
    const float* ln1_b   = (const float*)d_in[9];
    const float* ln2_s   = (const float*)d_in[10];
    const float* ln2_b   = (const float*)d_in[11];
    const float* ffn_w1  = (const float*)d_in[12];
    const float* ffn_b1  = (const float*)d_in[13];
    const float* ffn_w2  = (const float*)d_in[14];
    const float* ffn_b2  = (const float*)d_in[15];
    const float* lnf_s   = (const float*)d_in[16];
    const float* lnf_b   = (const float*)d_in[17];
    float* out = (float*)d_out;

    float *t_p, *h_p, *qkv_p, *o_p, *ffn_p, *patches_p, *tok_p, *wT_p;
    cudaGetSymbolAddress((void**)&t_p,       g_t);
    cudaGetSymbolAddress((void**)&h_p,       g_h);
    cudaGetSymbolAddress((void**)&qkv_p,     g_qkv);
    cudaGetSymbolAddress((void**)&o_p,       g_o);
    cudaGetSymbolAddress((void**)&ffn_p,     g_ffn);
    cudaGetSymbolAddress((void**)&patches_p, g_patches);
    cudaGetSymbolAddress((void**)&tok_p,     g_tok);
    cudaGetSymbolAddress((void**)&wT_p,      g_wT);

    cudaFuncSetAttribute(attn_kernel, cudaFuncAttributeMaxDynamicSharedMemorySize,
                         ATTN_SMEM);

    const int MB = (ROWS + BM - 1) / BM;   // 33

    // patch embedding
    im2col_kernel<<<4096, 256>>>(x);
    wtrans_kernel<<<768, 256>>>(conv_w);
    gemm_tf32_kernel<<<dim3(DMODEL/BN, 4096/BM), 256>>>(
        patches_p, wT_p, conv_b, nullptr, tok_p, 4096, 256, DMODEL, 0);
    assemble_kernel<<<(ROWS*DMODEL + 255)/256, 256>>>(cls, pos);

    for (int i = 0; i < DEPTH; i++) {
        ln_kernel<<<ROWS, 256>>>(t_p, ln1_s + i*DMODEL, ln1_b + i*DMODEL, h_p);
        gemm_tf32_kernel<<<dim3(QKVD/BN, MB), 256>>>(
            h_p, qkv_w + (size_t)i*DMODEL*QKVD, nullptr, nullptr,
            qkv_p, ROWS, DMODEL, QKVD, 0);
        attn_kernel<<<dim3(17, NHEAD, BATCH), 256, ATTN_SMEM>>>(qkv_p, o_p);
        gemm_tf32_kernel<<<dim3(DMODEL/BN, MB), 256>>>(
            o_p, merge_w + (size_t)i*HD*DMODEL, merge_b + i*DMODEL, t_p,
            t_p, ROWS, HD, DMODEL, 0);
        ln_kernel<<<ROWS, 256>>>(t_p, ln2_s + i*DMODEL, ln2_b + i*DMODEL, h_p);
        gemm_tf32_kernel<<<dim3(MLPD/BN, MB), 256>>>(
            h_p, ffn_w1 + (size_t)i*DMODEL*MLPD, ffn_b1 + i*MLPD, nullptr,
            ffn_p, ROWS, DMODEL, MLPD, 1);
        gemm_tf32_kernel<<<dim3(DMODEL/BN, MB), 256>>>(
            ffn_p, ffn_w2 + (size_t)i*MLPD*DMODEL, ffn_b2 + i*DMODEL, t_p,
            t_p, ROWS, MLPD, DMODEL, 0);
    }
    ln_kernel<<<ROWS, 256>>>(t_p, lnf_s, lnf_b, out);
}

// round 8
// speedup vs baseline: 2.7447x; 1.6256x over previous
#include <cuda_runtime.h>
#include <math.h>
#include <stdint.h>

// ---------------- problem constants ----------------
#define BATCH   4
#define NTOK    1025
#define DMODEL  768
#define NHEAD   8
#define DHEAD   64
#define QKVD    1536          // 3*H*DH = 3*8*64
#define HD      512           // H*DH
#define MLPD    2048
#define NPATCH  1024
#define ROWS    (BATCH*NTOK)  // 4100
#define DEPTH   12

// ---------------- scratch (device globals; no allocation allowed) ----------------
__device__ __align__(16) float g_t[BATCH*NTOK*DMODEL];        // residual stream
__device__ __align__(16) float g_h[BATCH*NTOK*DMODEL];        // LN output
__device__ __align__(16) float g_qkv[BATCH*NTOK*QKVD];
__device__ __align__(16) float g_o[BATCH*NTOK*HD];
__device__ __align__(16) float g_ffn[BATCH*NTOK*MLPD];
__device__ __align__(16) float g_patches[4096*256];
__device__ __align__(16) float g_tok[4096*DMODEL];
__device__ __align__(16) float g_wT[256*DMODEL];

// ---------------- helpers ----------------
__device__ __forceinline__ float gelu_exact(float x) {
    return 0.5f * x * (1.0f + erff(x * 0.70710678118654752f));
}
__device__ __forceinline__ float tf32r(float x) {
    uint32_t u;
    asm("cvt.rna.tf32.f32 %0, %1;" : "=r"(u) : "f"(x));
    return __uint_as_float(u);
}

// ---------------- im2col: extract 16x16 patches (C=1) ----------------
__global__ void im2col_kernel(const float* __restrict__ x) {
    int idx = blockIdx.x * blockDim.x + threadIdx.x;
    if (idx >= 4096*256) return;
    int k   = idx & 255;
    int row = idx >> 8;
    int b   = row >> 10;
    int pr  = row & 1023;
    int gy  = pr >> 5, gx = pr & 31;
    int p   = k >> 4,  q  = k & 15;
    g_patches[idx] = x[((size_t)(b*512 + gy*16 + p))*512 + gx*16 + q];
}

// ---------------- transpose conv_w [768,256] -> wT [256,768] ----------------
__global__ void wtrans_kernel(const float* __restrict__ w) {
    int idx = blockIdx.x * blockDim.x + threadIdx.x;
    if (idx >= 768*256) return;
    int d = idx >> 8, k = idx & 255;
    g_wT[k*DMODEL + d] = w[idx];
}

// ---------------- assemble t = concat(cls, tok) + pos ----------------
__global__ void assemble_kernel(const float* __restrict__ cls,
                                const float* __restrict__ pos) {
    int idx = blockIdx.x * blockDim.x + threadIdx.x;
    if (idx >= ROWS*DMODEL) return;
    int d = idx % DMODEL;
    int n = (idx / DMODEL) % NTOK;
    int b = idx / (DMODEL*NTOK);
    float v;
    if (n == 0) v = cls[d];
    else        v = g_tok[((size_t)(b*NPATCH + n - 1))*DMODEL + d];
    g_t[idx] = v + pos[n*DMODEL + d];
}

// ---------------- LayerNorm: one block per row of 768 ----------------
__global__ void ln_kernel(const float* __restrict__ x, const float* __restrict__ sc,
                          const float* __restrict__ bi, float* __restrict__ y) {
    int row = blockIdx.x;
    const float* xr = x + (size_t)row * DMODEL;
    float*       yr = y + (size_t)row * DMODEL;
    int tid = threadIdx.x;
    float v0 = xr[tid], v1 = xr[tid+256], v2 = xr[tid+512];
    float s1 = v0 + v1 + v2;
    float s2 = v0*v0 + v1*v1 + v2*v2;
    #pragma unroll
    for (int o = 16; o; o >>= 1) {
        s1 += __shfl_xor_sync(0xffffffffu, s1, o);
        s2 += __shfl_xor_sync(0xffffffffu, s2, o);
    }
    __shared__ float r1[8], r2[8];
    if ((tid & 31) == 0) { r1[tid>>5] = s1; r2[tid>>5] = s2; }
    __syncthreads();
    float t1 = 0.f, t2 = 0.f;
    #pragma unroll
    for (int w = 0; w < 8; w++) { t1 += r1[w]; t2 += r2[w]; }
    float mean = t1 * (1.0f/768.0f);
    float var  = t2 * (1.0f/768.0f) - mean*mean;
    float rstd = rsqrtf(var + 1e-5f);
    yr[tid]     = (v0-mean)*rstd*sc[tid]     + bi[tid];
    yr[tid+256] = (v1-mean)*rstd*sc[tid+256] + bi[tid+256];
    yr[tid+512] = (v2-mean)*rstd*sc[tid+512] + bi[tid+512];
}

// ---------------- TF32 tensor-core GEMM (unchanged from R7-passing version) ----
#define BM 128
#define BN 128
#define BK 16
#define APAD 20
#define BPAD 136

__global__ void __launch_bounds__(256)
gemm_tf32_kernel(const float* __restrict__ A, const float* __restrict__ Bm,
                 const float* __restrict__ bias, const float* __restrict__ res,
                 float* __restrict__ C, int M, int K, int Nn, int act) {
    __shared__ float As[2][BM][APAD];
    __shared__ float Bs[2][BK][BPAD];

    int tid  = threadIdx.x;
    int warp = tid >> 5, lane = tid & 31;
    int g = lane >> 2, t = lane & 3;
    int wm = (warp >> 1) * 32;
    int wn = (warp & 1) * 64;
    int bm = blockIdx.y * BM, bn = blockIdx.x * BN;

    int ar[2], ac[2], br[2], bc[2];
    #pragma unroll
    for (int l = 0; l < 2; l++) {
        int idx = tid + l*256;
        ar[l] = idx >> 2;  ac[l] = (idx & 3) * 4;
        br[l] = idx >> 5;  bc[l] = (idx & 31) * 4;
    }

    float acc[2][8][4];
    #pragma unroll
    for (int mt = 0; mt < 2; mt++)
        #pragma unroll
        for (int nt = 0; nt < 8; nt++)
            #pragma unroll
            for (int j = 0; j < 4; j++) acc[mt][nt][j] = 0.f;

    int ntiles = K / BK;

    #pragma unroll
    for (int l = 0; l < 2; l++) {
        int grow = bm + ar[l];
        float4 v = make_float4(0.f,0.f,0.f,0.f);
        if (grow < M) v = *(const float4*)&A[(size_t)grow*K + ac[l]];
        As[0][ar[l]][ac[l]+0] = tf32r(v.x);
        As[0][ar[l]][ac[l]+1] = tf32r(v.y);
        As[0][ar[l]][ac[l]+2] = tf32r(v.z);
        As[0][ar[l]][ac[l]+3] = tf32r(v.w);
        float4 w = *(const float4*)&Bm[(size_t)br[l]*Nn + bn + bc[l]];
        Bs[0][br[l]][bc[l]+0] = tf32r(w.x);
        Bs[0][br[l]][bc[l]+1] = tf32r(w.y);
        Bs[0][br[l]][bc[l]+2] = tf32r(w.z);
        Bs[0][br[l]][bc[l]+3] = tf32r(w.w);
    }
    __syncthreads();

    int buf = 0;
    for (int kt = 0; kt < ntiles; kt++) {
        float4 pa[2], pb[2];
        bool has = (kt + 1) < ntiles;
        if (has) {
            int k0n = (kt + 1) * BK;
            #pragma unroll
            for (int l = 0; l < 2; l++) {
                int grow = bm + ar[l];
                pa[l] = make_float4(0.f,0.f,0.f,0.f);
                if (grow < M) pa[l] = *(const float4*)&A[(size_t)grow*K + k0n + ac[l]];
                pb[l] = *(const float4*)&Bm[(size_t)(k0n + br[l])*Nn + bn + bc[l]];
            }
        }

        #pragma unroll
        for (int ks = 0; ks < BK; ks += 8) {
            uint32_t af[2][4], bf[8][2];
            #pragma unroll
            for (int mt = 0; mt < 2; mt++) {
                int r0 = wm + mt*16 + g;
                af[mt][0] = __float_as_uint(As[buf][r0    ][ks + t    ]);
                af[mt][1] = __float_as_uint(As[buf][r0 + 8][ks + t    ]);
                af[mt][2] = __float_as_uint(As[buf][r0    ][ks + t + 4]);
                af[mt][3] = __float_as_uint(As[buf][r0 + 8][ks + t + 4]);
            }
            #pragma unroll
            for (int nt = 0; nt < 8; nt++) {
                int cn = wn + nt*8 + g;
                bf[nt][0] = __float_as_uint(Bs[buf][ks + t    ][cn]);
                bf[nt][1] = __float_as_uint(Bs[buf][ks + t + 4][cn]);
            }
            #pragma unroll
            for (int mt = 0; mt < 2; mt++)
                #pragma unroll
                for (int nt = 0; nt < 8; nt++) {
                    asm volatile(
                        "mma.sync.aligned.m16n8k8.row.col.f32.tf32.tf32.f32 "
                        "{%0,%1,%2,%3}, {%4,%5,%6,%7}, {%8,%9}, {%0,%1,%2,%3};"
                        : "+f"(acc[mt][nt][0]), "+f"(acc[mt][nt][1]),
                          "+f"(acc[mt][nt][2]), "+f"(acc[mt][nt][3])
                        : "r"(af[mt][0]), "r"(af[mt][1]), "r"(af[mt][2]), "r"(af[mt][3]),
                          "r"(bf[nt][0]), "r"(bf[nt][1]));
                }
        }

        if (has) {
            int nb = buf ^ 1;
            #pragma unroll
            for (int l = 0; l < 2; l++) {
                As[nb][ar[l]][ac[l]+0] = tf32r(pa[l].x);
                As[nb][ar[l]][ac[l]+1] = tf32r(pa[l].y);
                As[nb][ar[l]][ac[l]+2] = tf32r(pa[l].z);
                As[nb][ar[l]][ac[l]+3] = tf32r(pa[l].w);
                Bs[nb][br[l]][bc[l]+0] = tf32r(pb[l].x);
                Bs[nb][br[l]][bc[l]+1] = tf32r(pb[l].y);
                Bs[nb][br[l]][bc[l]+2] = tf32r(pb[l].z);
                Bs[nb][br[l]][bc[l]+3] = tf32r(pb[l].w);
            }
        }
        __syncthreads();
        buf ^= 1;
    }

    #pragma unroll
    for (int nt = 0; nt < 8; nt++) {
        int col = bn + wn + nt*8 + 2*t;
        float2 bi2 = make_float2(0.f, 0.f);
        if (bias) bi2 = *(const float2*)&bias[col];
        #pragma unroll
        for (int mt = 0; mt < 2; mt++) {
            int r0 = bm + wm + mt*16 + g;
            #pragma unroll
            for (int half = 0; half < 2; half++) {
                int row = r0 + half*8;
                if (row >= M) continue;
                float vx = acc[mt][nt][2*half + 0] + bi2.x;
                float vy = acc[mt][nt][2*half + 1] + bi2.y;
                if (act == 1) { vx = gelu_exact(vx); vy = gelu_exact(vy); }
                if (res) {
                    float2 r2 = *(const float2*)&res[(size_t)row*Nn + col];
                    vx += r2.x; vy += r2.y;
                }
                float2 o2 = make_float2(vx, vy);
                *(float2*)&C[(size_t)row*Nn + col] = o2;
            }
        }
    }
}

// ---------------- TF32 mma flash attention ----------------
// grid (17, 8, 4), 128 threads = 4 warps. Each warp: 16 queries x all 64 keys.
// S = Q K^T and O += P V both via m16n8k8 tf32 mma.
// Pitches: K/P = 68 (4g+t conflict-free), V = 72 (8t+g conflict-free).
#define KPITCH 68
#define VPITCH 72
#define PPITCH 68
#define ATTN_SMEM ((64*KPITCH + 64*VPITCH + 64*PPITCH)*4)   // 53,248 B

__global__ void __launch_bounds__(128)
attn_mma_kernel(const float* __restrict__ qkv, float* __restrict__ o) {
    extern __shared__ float sm[];
    float* Ks = sm;
    float* Vs = sm + 64*KPITCH;
    float* Ps = sm + 64*KPITCH + 64*VPITCH;   // also Q staging before mainloop

    int tid  = threadIdx.x;
    int warp = tid >> 5, lane = tid & 31;
    int g = lane >> 2, t = lane & 3;
    int qt = blockIdx.x, h = blockIdx.y, b = blockIdx.z;
    const float* qkvb = qkv + (size_t)b*NTOK*QKVD + h*192;

    // stage Q tile [64 x 64] into Ps region (tf32-rounded)
    #pragma unroll
    for (int it = 0; it < 8; it++) {
        int idx = tid + it*128;
        int r = idx >> 4, c4 = (idx & 15) * 4;
        int qn = qt*64 + r;
        float4 qv = make_float4(0.f,0.f,0.f,0.f);
        if (qn < NTOK) qv = *(const float4*)(qkvb + (size_t)qn*QKVD + c4);
        Ps[r*PPITCH + c4+0] = tf32r(qv.x);
        Ps[r*PPITCH + c4+1] = tf32r(qv.y);
        Ps[r*PPITCH + c4+2] = tf32r(qv.z);
        Ps[r*PPITCH + c4+3] = tf32r(qv.w);
    }
    __syncthreads();

    // load Q A-fragments (register-resident for all 17 K-tiles)
    uint32_t qf[8][4];
    {
        const float* Pw = Ps + warp*16*PPITCH;
        #pragma unroll
        for (int ks = 0; ks < 8; ks++) {
            qf[ks][0] = __float_as_uint(Pw[ g     *PPITCH + ks*8 + t    ]);
            qf[ks][1] = __float_as_uint(Pw[(g+8)  *PPITCH + ks*8 + t    ]);
            qf[ks][2] = __float_as_uint(Pw[ g     *PPITCH + ks*8 + t + 4]);
            qf[ks][3] = __float_as_uint(Pw[(g+8)  *PPITCH + ks*8 + t + 4]);
        }
    }

    float m0 = -1e30f, m1 = -1e30f, l0 = 0.f, l1 = 0.f;
    float oacc[8][4];
    #pragma unroll
    for (int nt = 0; nt < 8; nt++)
        #pragma unroll
        for (int j = 0; j < 4; j++) oacc[nt][j] = 0.f;

    float* Pw = Ps + warp*16*PPITCH;

    for (int kt = 0; kt < 17; kt++) {
        __syncthreads();   // prior iteration's Ks/Vs reads (and Q-frag loads) done
        #pragma unroll
        for (int it = 0; it < 8; it++) {
            int idx = tid + it*128;
            int r = idx >> 4, c4 = (idx & 15) * 4;
            int kn = kt*64 + r;
            float4 kv = make_float4(0.f,0.f,0.f,0.f);
            float4 vv = make_float4(0.f,0.f,0.f,0.f);
            if (kn < NTOK) {
                const float* base = qkvb + (size_t)kn*QKVD;
                kv = *(const float4*)(base + 64  + c4);
                vv = *(const float4*)(base + 128 + c4);
            }
            Ks[r*KPITCH + c4+0] = tf32r(kv.x);
            Ks[r*KPITCH + c4+1] = tf32r(kv.y);
            Ks[r*KPITCH + c4+2] = tf32r(kv.z);
            Ks[r*KPITCH + c4+3] = tf32r(kv.w);
            Vs[r*VPITCH + c4+0] = tf32r(vv.x);
            Vs[r*VPITCH + c4+1] = tf32r(vv.y);
            Vs[r*VPITCH + c4+2] = tf32r(vv.z);
            Vs[r*VPITCH + c4+3] = tf32r(vv.w);
        }
        __syncthreads();

        // S = Q K^T  (C-frag: rows g/g+8, cols nt*8+2t/+1)
        float sf[8][4];
        #pragma unroll
        for (int nt = 0; nt < 8; nt++)
            #pragma unroll
            for (int j = 0; j < 4; j++) sf[nt][j] = 0.f;
        #pragma unroll
        for (int ks = 0; ks < 8; ks++) {
            uint32_t bf[8][2];
            #pragma unroll
            for (int nt = 0; nt < 8; nt++) {
                bf[nt][0] = __float_as_uint(Ks[(nt*8+g)*KPITCH + ks*8 + t    ]);
                bf[nt][1] = __float_as_uint(Ks[(nt*8+g)*KPITCH + ks*8 + t + 4]);
            }
            #pragma unroll
            for (int nt = 0; nt < 8; nt++) {
                asm volatile(
                    "mma.sync.aligned.m16n8k8.row.col.f32.tf32.tf32.f32 "
                    "{%0,%1,%2,%3}, {%4,%5,%6,%7}, {%8,%9}, {%0,%1,%2,%3};"
                    : "+f"(sf[nt][0]), "+f"(sf[nt][1]), "+f"(sf[nt][2]), "+f"(sf[nt][3])
                    : "r"(qf[ks][0]), "r"(qf[ks][1]), "r"(qf[ks][2]), "r"(qf[ks][3]),
                      "r"(bf[nt][0]), "r"(bf[nt][1]));
            }
        }

        // scale + mask + row max (rows g and g+8)
        float mx0 = -1e30f, mx1 = -1e30f;
        #pragma unroll
        for (int nt = 0; nt < 8; nt++) {
            int c0 = kt*64 + nt*8 + 2*t;
            bool v0 = c0 < NTOK, v1 = (c0+1) < NTOK;
            sf[nt][0] = v0 ? sf[nt][0]*0.125f : -1e30f;
            sf[nt][1] = v1 ? sf[nt][1]*0.125f : -1e30f;
            sf[nt][2] = v0 ? sf[nt][2]*0.125f : -1e30f;
            sf[nt][3] = v1 ? sf[nt][3]*0.125f : -1e30f;
            mx0 = fmaxf(mx0, fmaxf(sf[nt][0], sf[nt][1]));
            mx1 = fmaxf(mx1, fmaxf(sf[nt][2], sf[nt][3]));
        }
        #pragma unroll
        for (int off = 1; off <= 2; off <<= 1) {
            mx0 = fmaxf(mx0, __shfl_xor_sync(0xffffffffu, mx0, off));
            mx1 = fmaxf(mx1, __shfl_xor_sync(0xffffffffu, mx1, off));
        }
        float mn0 = fmaxf(m0, mx0), mn1 = fmaxf(m1, mx1);
        float a0 = __expf(m0 - mn0), a1 = __expf(m1 - mn1);
        m0 = mn0; m1 = mn1;

        float rs0 = 0.f, rs1 = 0.f;
        #pragma unroll
        for (int nt = 0; nt < 8; nt++) {
            sf[nt][0] = __expf(sf[nt][0] - mn0);
            sf[nt][1] = __expf(sf[nt][1] - mn0);
            sf[nt][2] = __expf(sf[nt][2] - mn1);
            sf[nt][3] = __expf(sf[nt][3] - mn1);
            rs0 += sf[nt][0] + sf[nt][1];
            rs1 += sf[nt][2] + sf[nt][3];
        }
        #pragma unroll
        for (int off = 1; off <= 2; off <<= 1) {
            rs0 += __shfl_xor_sync(0xffffffffu, rs0, off);
            rs1 += __shfl_xor_sync(0xffffffffu, rs1, off);
        }
        l0 = l0*a0 + rs0; l1 = l1*a1 + rs1;
        #pragma unroll
        for (int nt = 0; nt < 8; nt++) {
            oacc[nt][0] *= a0; oacc[nt][1] *= a0;
            oacc[nt][2] *= a1; oacc[nt][3] *= a1;
        }

        // write P (C-frag layout) to per-warp smem slice, tf32-rounded
        #pragma unroll
        for (int nt = 0; nt < 8; nt++) {
            Pw[ g   *PPITCH + nt*8 + 2*t    ] = tf32r(sf[nt][0]);
            Pw[ g   *PPITCH + nt*8 + 2*t + 1] = tf32r(sf[nt][1]);
            Pw[(g+8)*PPITCH + nt*8 + 2*t    ] = tf32r(sf[nt][2]);
            Pw[(g+8)*PPITCH + nt*8 + 2*t + 1] = tf32r(sf[nt][3]);
        }
        __syncwarp();

        // O += P V
        #pragma unroll
        for (int ks = 0; ks < 8; ks++) {
            uint32_t pf[4];
            pf[0] = __float_as_uint(Pw[ g   *PPITCH + ks*8 + t    ]);
            pf[1] = __float_as_uint(Pw[(g+8)*PPITCH + ks*8 + t    ]);
            pf[2] = __float_as_uint(Pw[ g   *PPITCH + ks*8 + t + 4]);
            pf[3] = __float_as_uint(Pw[(g+8)*PPITCH + ks*8 + t + 4]);
            #pragma unroll
            for (int nt = 0; nt < 8; nt++) {
                uint32_t vf0 = __float_as_uint(Vs[(ks*8 + t    )*VPITCH + nt*8 + g]);
                uint32_t vf1 = __float_as_uint(Vs[(ks*8 + t + 4)*VPITCH + nt*8 + g]);
                asm volatile(
                    "mma.sync.aligned.m16n8k8.row.col.f32.tf32.tf32.f32 "
                    "{%0,%1,%2,%3}, {%4,%5,%6,%7}, {%8,%9}, {%0,%1,%2,%3};"
                    : "+f"(oacc[nt][0]), "+f"(oacc[nt][1]), "+f"(oacc[nt][2]), "+f"(oacc[nt][3])
                    : "r"(pf[0]), "r"(pf[1]), "r"(pf[2]), "r"(pf[3]),
                      "r"(vf0), "r"(vf1));
            }
        }
        __syncwarp();   // Pw reads done before next iteration's writes
    }

    // epilogue
    float inv0 = 1.0f / l0, inv1 = 1.0f / l1;
    int n0 = qt*64 + warp*16 + g;
    int n1 = n0 + 8;
    #pragma unroll
    for (int nt = 0; nt < 8; nt++) {
        int col = h*64 + nt*8 + 2*t;
        if (n0 < NTOK) {
            float2 v = make_float2(oacc[nt][0]*inv0, oacc[nt][1]*inv0);
            *(float2*)&o[(size_t)(b*NTOK + n0)*HD + col] = v;
        }
        if (n1 < NTOK) {
            float2 v = make_float2(oacc[nt][2]*inv1, oacc[nt][3]*inv1);
            *(float2*)&o[(size_t)(b*NTOK + n1)*HD + col] = v;
        }
    }
}

// ---------------- driver ----------------
extern "C" void kernel_launch(void* const* d_in, const int* in_sizes, int n_in,
                              void* d_out, int out_size) {
    const float* x       = (const float*)d_in[0];
    const float* conv_w  = (const float*)d_in[1];
    const float* conv_b  = (const float*)d_in[2];
    const float* cls     = (const float*)d_in[3];
    const float* pos     = (const float*)d_in[4];
    const float* qkv_w   = (const float*)d_in[5];
    const float* merge_w = (const float*)d_in[6];
    const float* merge_b = (const float*)d_in[7];
    const float* ln1_s   = (const float*)d_in[8];
    const float* ln1_b   = (const float*)d_in[9];
    const float* ln2_s   = (const float*)d_in[10];
    const float* ln2_b   = (const float*)d_in[11];
    const float* ffn_w1  = (const float*)d_in[12];
    const float* ffn_b1  = (const float*)d_in[13];
    const float* ffn_w2  = (const float*)d_in[14];
    const float* ffn_b2  = (const float*)d_in[15];
    const float* lnf_s   = (const float*)d_in[16];
    const float* lnf_b   = (const float*)d_in[17];
    float* out = (float*)d_out;

    float *t_p, *h_p, *qkv_p, *o_p, *ffn_p, *patches_p, *tok_p, *wT_p;
    cudaGetSymbolAddress((void**)&t_p,       g_t);
    cudaGetSymbolAddress((void**)&h_p,       g_h);
    cudaGetSymbolAddress((void**)&qkv_p,     g_qkv);
    cudaGetSymbolAddress((void**)&o_p,       g_o);
    cudaGetSymbolAddress((void**)&ffn_p,     g_ffn);
    cudaGetSymbolAddress((void**)&patches_p, g_patches);
    cudaGetSymbolAddress((void**)&tok_p,     g_tok);
    cudaGetSymbolAddress((void**)&wT_p,      g_wT);

    cudaFuncSetAttribute(attn_mma_kernel, cudaFuncAttributeMaxDynamicSharedMemorySize,
                         ATTN_SMEM);

    const int MB = (ROWS + BM - 1) / BM;   // 33

    // patch embedding
    im2col_kernel<<<4096, 256>>>(x);
    wtrans_kernel<<<768, 256>>>(conv_w);
    gemm_tf32_kernel<<<dim3(DMODEL/BN, 4096/BM), 256>>>(
        patches_p, wT_p, conv_b, nullptr, tok_p, 4096, 256, DMODEL, 0);
    assemble_kernel<<<(ROWS*DMODEL + 255)/256, 256>>>(cls, pos);

    for (int i = 0; i < DEPTH; i++) {
        ln_kernel<<<ROWS, 256>>>(t_p, ln1_s + i*DMODEL, ln1_b + i*DMODEL, h_p);
        gemm_tf32_kernel<<<dim3(QKVD/BN, MB), 256>>>(
            h_p, qkv_w + (size_t)i*DMODEL*QKVD, nullptr, nullptr,
            qkv_p, ROWS, DMODEL, QKVD, 0);
        attn_mma_kernel<<<dim3(17, NHEAD, BATCH), 128, ATTN_SMEM>>>(qkv_p, o_p);
        gemm_tf32_kernel<<<dim3(DMODEL/BN, MB), 256>>>(
            o_p, merge_w + (size_t)i*HD*DMODEL, merge_b + i*DMODEL, t_p,
            t_p, ROWS, HD, DMODEL, 0);
        ln_kernel<<<ROWS, 256>>>(t_p, ln2_s + i*DMODEL, ln2_b + i*DMODEL, h_p);
        gemm_tf32_kernel<<<dim3(MLPD/BN, MB), 256>>>(
            h_p, ffn_w1 + (size_t)i*DMODEL*MLPD, ffn_b1 + i*MLPD, nullptr,
            ffn_p, ROWS, DMODEL, MLPD, 1);
        gemm_tf32_kernel<<<dim3(DMODEL/BN, MB), 256>>>(
            ffn_p, ffn_w2 + (size_t)i*MLPD*DMODEL, ffn_b2 + i*DMODEL, t_p,
            t_p, ROWS, MLPD, DMODEL, 0);
    }
    ln_kernel<<<ROWS, 256>>>(t_p, lnf_s, lnf_b, out);
}

// round 9
// speedup vs baseline: 3.2187x; 1.1727x over previous
#include <cuda_runtime.h>
#include <math.h>
#include <stdint.h>

// ---------------- problem constants ----------------
#define BATCH   4
#define NTOK    1025
#define DMODEL  768
#define NHEAD   8
#define DHEAD   64
#define QKVD    1536          // 3*H*DH = 3*8*64
#define HD      512           // H*DH
#define MLPD    2048
#define NPATCH  1024
#define ROWS    (BATCH*NTOK)  // 4100
#define DEPTH   12

// ---------------- scratch (device globals; no allocation allowed) ----------------
__device__ __align__(16) float g_t[BATCH*NTOK*DMODEL];        // residual stream
__device__ __align__(16) float g_h[BATCH*NTOK*DMODEL];        // LN output (tf32)
__device__ __align__(16) float g_qkv[BATCH*NTOK*QKVD];
__device__ __align__(16) float g_o[BATCH*NTOK*HD];            // attn out (tf32)
__device__ __align__(16) float g_ffn[BATCH*NTOK*MLPD];        // gelu out (tf32)
__device__ __align__(16) float g_patches[4096*256];           // tf32
__device__ __align__(16) float g_tok[4096*DMODEL];
__device__ __align__(16) float g_wT[256*DMODEL];              // tf32
// pre-rounded tf32 weights
__device__ __align__(16) float g_wqkv[DEPTH*DMODEL*QKVD];
__device__ __align__(16) float g_wmrg[DEPTH*HD*DMODEL];
__device__ __align__(16) float g_wf1 [DEPTH*DMODEL*MLPD];
__device__ __align__(16) float g_wf2 [DEPTH*MLPD*DMODEL];

// ---------------- helpers ----------------
__device__ __forceinline__ float gelu_exact(float x) {
    return 0.5f * x * (1.0f + erff(x * 0.70710678118654752f));
}
__device__ __forceinline__ float tf32r(float x) {
    uint32_t u;
    asm("cvt.rna.tf32.f32 %0, %1;" : "=r"(u) : "f"(x));
    return __uint_as_float(u);
}
__device__ __forceinline__ void cp16z(uint32_t dst, const void* src, bool pred) {
    int sz = pred ? 16 : 0;
    asm volatile("cp.async.cg.shared.global [%0], [%1], 16, %2;"
                 :: "r"(dst), "l"(src), "r"(sz));
}
__device__ __forceinline__ void cp_commit() {
    asm volatile("cp.async.commit_group;");
}
template<int N>
__device__ __forceinline__ void cp_wait() {
    asm volatile("cp.async.wait_group %0;" :: "n"(N));
}

// ---------------- weight pre-round: dst = tf32(src) ----------------
__global__ void wround_kernel(const float* __restrict__ w, float* __restrict__ dst, int n) {
    int i = blockIdx.x * blockDim.x + threadIdx.x;
    if (i < n) dst[i] = tf32r(w[i]);
}

// ---------------- im2col (tf32-rounded output) ----------------
__global__ void im2col_kernel(const float* __restrict__ x) {
    int idx = blockIdx.x * blockDim.x + threadIdx.x;
    if (idx >= 4096*256) return;
    int k   = idx & 255;
    int row = idx >> 8;
    int b   = row >> 10;
    int pr  = row & 1023;
    int gy  = pr >> 5, gx = pr & 31;
    int p   = k >> 4,  q  = k & 15;
    g_patches[idx] = tf32r(x[((size_t)(b*512 + gy*16 + p))*512 + gx*16 + q]);
}

// ---------------- transpose conv_w (tf32-rounded) ----------------
__global__ void wtrans_kernel(const float* __restrict__ w) {
    int idx = blockIdx.x * blockDim.x + threadIdx.x;
    if (idx >= 768*256) return;
    int d = idx >> 8, k = idx & 255;
    g_wT[k*DMODEL + d] = tf32r(w[idx]);
}

// ---------------- assemble t = concat(cls, tok) + pos (full fp32) ----------------
__global__ void assemble_kernel(const float* __restrict__ cls,
                                const float* __restrict__ pos) {
    int idx = blockIdx.x * blockDim.x + threadIdx.x;
    if (idx >= ROWS*DMODEL) return;
    int d = idx % DMODEL;
    int n = (idx / DMODEL) % NTOK;
    int b = idx / (DMODEL*NTOK);
    float v;
    if (n == 0) v = cls[d];
    else        v = g_tok[((size_t)(b*NPATCH + n - 1))*DMODEL + d];
    g_t[idx] = v + pos[n*DMODEL + d];
}

// ---------------- LayerNorm (optionally tf32-rounded output) ----------------
__global__ void ln_kernel(const float* __restrict__ x, const float* __restrict__ sc,
                          const float* __restrict__ bi, float* __restrict__ y, int rnd) {
    int row = blockIdx.x;
    const float* xr = x + (size_t)row * DMODEL;
    float*       yr = y + (size_t)row * DMODEL;
    int tid = threadIdx.x;
    float v0 = xr[tid], v1 = xr[tid+256], v2 = xr[tid+512];
    float s1 = v0 + v1 + v2;
    float s2 = v0*v0 + v1*v1 + v2*v2;
    #pragma unroll
    for (int o = 16; o; o >>= 1) {
        s1 += __shfl_xor_sync(0xffffffffu, s1, o);
        s2 += __shfl_xor_sync(0xffffffffu, s2, o);
    }
    __shared__ float r1[8], r2[8];
    if ((tid & 31) == 0) { r1[tid>>5] = s1; r2[tid>>5] = s2; }
    __syncthreads();
    float t1 = 0.f, t2 = 0.f;
    #pragma unroll
    for (int w = 0; w < 8; w++) { t1 += r1[w]; t2 += r2[w]; }
    float mean = t1 * (1.0f/768.0f);
    float var  = t2 * (1.0f/768.0f) - mean*mean;
    float rstd = rsqrtf(var + 1e-5f);
    float o0 = (v0-mean)*rstd*sc[tid]     + bi[tid];
    float o1 = (v1-mean)*rstd*sc[tid+256] + bi[tid+256];
    float o2 = (v2-mean)*rstd*sc[tid+512] + bi[tid+512];
    if (rnd) { o0 = tf32r(o0); o1 = tf32r(o1); o2 = tf32r(o2); }
    yr[tid] = o0; yr[tid+256] = o1; yr[tid+512] = o2;
}

// ---------------- TF32 tensor-core GEMM, cp.async 3-stage pipeline ----------------
// Inputs A and Bm MUST already be tf32-rounded. C = act(A@B + bias) + res.
#define BM 128
#define BN 128
#define BK 16
#define APAD 20
#define BPAD 136
#define STAGES 3
#define STAGE_FLOATS (BM*APAD + BK*BPAD)          // 4736
#define GEMM_SMEM (STAGES*STAGE_FLOATS*4)         // 56,832 B

__global__ void __launch_bounds__(256)
gemm_tf32_kernel(const float* __restrict__ A, const float* __restrict__ Bm,
                 const float* __restrict__ bias, const float* __restrict__ res,
                 float* __restrict__ C, int M, int K, int Nn, int act) {
    extern __shared__ float smem[];
    uint32_t smem_base = (uint32_t)__cvta_generic_to_shared(smem);

    int tid  = threadIdx.x;
    int warp = tid >> 5, lane = tid & 31;
    int g = lane >> 2, t = lane & 3;
    int wm = (warp >> 1) * 32;
    int wn = (warp & 1) * 64;
    int bm = blockIdx.y * BM, bn = blockIdx.x * BN;

    int ar[2], ac[2], br[2], bc[2];
    #pragma unroll
    for (int l = 0; l < 2; l++) {
        int idx = tid + l*256;
        ar[l] = idx >> 2;  ac[l] = (idx & 3) * 4;
        br[l] = idx >> 5;  bc[l] = (idx & 31) * 4;
    }

    float acc[2][8][4];
    #pragma unroll
    for (int mt = 0; mt < 2; mt++)
        #pragma unroll
        for (int nt = 0; nt < 8; nt++)
            #pragma unroll
            for (int j = 0; j < 4; j++) acc[mt][nt][j] = 0.f;

    int ntiles = K / BK;

    // issue tile kt into stage s
    #define ISSUE_TILE(s_, kt_) do {                                            \
        int k0_ = (kt_) * BK;                                                   \
        uint32_t sb_ = smem_base + (uint32_t)((s_)*STAGE_FLOATS)*4u;            \
        _Pragma("unroll")                                                       \
        for (int l = 0; l < 2; l++) {                                           \
            int grow_ = bm + ar[l];                                             \
            cp16z(sb_ + (uint32_t)(ar[l]*APAD + ac[l])*4u,                      \
                  &A[(size_t)grow_*K + k0_ + ac[l]], grow_ < M);                \
            cp16z(sb_ + (uint32_t)(BM*APAD + br[l]*BPAD + bc[l])*4u,            \
                  &Bm[(size_t)(k0_ + br[l])*Nn + bn + bc[l]], true);            \
        }                                                                       \
    } while (0)

    // prologue: stages 0..STAGES-2
    #pragma unroll
    for (int s = 0; s < STAGES-1; s++) {
        ISSUE_TILE(s, s);
        cp_commit();
    }

    for (int kt = 0; kt < ntiles; kt++) {
        cp_wait<STAGES-2>();     // tile kt resident
        __syncthreads();         // all warps done with the stage being overwritten

        int nk = kt + STAGES - 1;
        if (nk < ntiles) ISSUE_TILE(nk % STAGES, nk);
        cp_commit();

        const float* As_s = smem + (kt % STAGES)*STAGE_FLOATS;
        const float* Bs_s = As_s + BM*APAD;

        #pragma unroll
        for (int ks = 0; ks < BK; ks += 8) {
            uint32_t af[2][4], bf[8][2];
            #pragma unroll
            for (int mt = 0; mt < 2; mt++) {
                int r0 = wm + mt*16 + g;
                af[mt][0] = __float_as_uint(As_s[ r0     *APAD + ks + t    ]);
                af[mt][1] = __float_as_uint(As_s[(r0 + 8)*APAD + ks + t    ]);
                af[mt][2] = __float_as_uint(As_s[ r0     *APAD + ks + t + 4]);
                af[mt][3] = __float_as_uint(As_s[(r0 + 8)*APAD + ks + t + 4]);
            }
            #pragma unroll
            for (int nt = 0; nt < 8; nt++) {
                int cn = wn + nt*8 + g;
                bf[nt][0] = __float_as_uint(Bs_s[(ks + t    )*BPAD + cn]);
                bf[nt][1] = __float_as_uint(Bs_s[(ks + t + 4)*BPAD + cn]);
            }
            #pragma unroll
            for (int mt = 0; mt < 2; mt++)
                #pragma unroll
                for (int nt = 0; nt < 8; nt++) {
                    asm volatile(
                        "mma.sync.aligned.m16n8k8.row.col.f32.tf32.tf32.f32 "
                        "{%0,%1,%2,%3}, {%4,%5,%6,%7}, {%8,%9}, {%0,%1,%2,%3};"
                        : "+f"(acc[mt][nt][0]), "+f"(acc[mt][nt][1]),
                          "+f"(acc[mt][nt][2]), "+f"(acc[mt][nt][3])
                        : "r"(af[mt][0]), "r"(af[mt][1]), "r"(af[mt][2]), "r"(af[mt][3]),
                          "r"(bf[nt][0]), "r"(bf[nt][1]));
                }
        }
        __syncthreads();   // compute done before this stage is rewritten
    }

    // epilogue: bias -> (gelu) -> (+res) -> store; round when act==1 (feeds next GEMM A)
    #pragma unroll
    for (int nt = 0; nt < 8; nt++) {
        int col = bn + wn + nt*8 + 2*t;
        float2 bi2 = make_float2(0.f, 0.f);
        if (bias) bi2 = *(const float2*)&bias[col];
        #pragma unroll
        for (int mt = 0; mt < 2; mt++) {
            int r0 = bm + wm + mt*16 + g;
            #pragma unroll
            for (int half = 0; half < 2; half++) {
                int row = r0 + half*8;
                if (row >= M) continue;
                float vx = acc[mt][nt][2*half + 0] + bi2.x;
                float vy = acc[mt][nt][2*half + 1] + bi2.y;
                if (act == 1) {
                    vx = tf32r(gelu_exact(vx));
                    vy = tf32r(gelu_exact(vy));
                }
                if (res) {
                    float2 r2 = *(const float2*)&res[(size_t)row*Nn + col];
                    vx += r2.x; vy += r2.y;
                }
                float2 o2 = make_float2(vx, vy);
                *(float2*)&C[(size_t)row*Nn + col] = o2;
            }
        }
    }
}

// ---------------- TF32 mma flash attention (unchanged; output tf32-rounded) ------
#define KPITCH 68
#define VPITCH 72
#define PPITCH 68
#define ATTN_SMEM ((64*KPITCH + 64*VPITCH + 64*PPITCH)*4)

__global__ void __launch_bounds__(128)
attn_mma_kernel(const float* __restrict__ qkv, float* __restrict__ o) {
    extern __shared__ float sm[];
    float* Ks = sm;
    float* Vs = sm + 64*KPITCH;
    float* Ps = sm + 64*KPITCH + 64*VPITCH;

    int tid  = threadIdx.x;
    int warp = tid >> 5, lane = tid & 31;
    int g = lane >> 2, t = lane & 3;
    int qt = blockIdx.x, h = blockIdx.y, b = blockIdx.z;
    const float* qkvb = qkv + (size_t)b*NTOK*QKVD + h*192;

    #pragma unroll
    for (int it = 0; it < 8; it++) {
        int idx = tid + it*128;
        int r = idx >> 4, c4 = (idx & 15) * 4;
        int qn = qt*64 + r;
        float4 qv = make_float4(0.f,0.f,0.f,0.f);
        if (qn < NTOK) qv = *(const float4*)(qkvb + (size_t)qn*QKVD + c4);
        Ps[r*PPITCH + c4+0] = tf32r(qv.x);
        Ps[r*PPITCH + c4+1] = tf32r(qv.y);
        Ps[r*PPITCH + c4+2] = tf32r(qv.z);
        Ps[r*PPITCH + c4+3] = tf32r(qv.w);
    }
    __syncthreads();

    uint32_t qf[8][4];
    {
        const float* Pw = Ps + warp*16*PPITCH;
        #pragma unroll
        for (int ks = 0; ks < 8; ks++) {
            qf[ks][0] = __float_as_uint(Pw[ g     *PPITCH + ks*8 + t    ]);
            qf[ks][1] = __float_as_uint(Pw[(g+8)  *PPITCH + ks*8 + t    ]);
            qf[ks][2] = __float_as_uint(Pw[ g     *PPITCH + ks*8 + t + 4]);
            qf[ks][3] = __float_as_uint(Pw[(g+8)  *PPITCH + ks*8 + t + 4]);
        }
    }

    float m0 = -1e30f, m1 = -1e30f, l0 = 0.f, l1 = 0.f;
    float oacc[8][4];
    #pragma unroll
    for (int nt = 0; nt < 8; nt++)
        #pragma unroll
        for (int j = 0; j < 4; j++) oacc[nt][j] = 0.f;

    float* Pw = Ps + warp*16*PPITCH;

    for (int kt = 0; kt < 17; kt++) {
        __syncthreads();
        #pragma unroll
        for (int it = 0; it < 8; it++) {
            int idx = tid + it*128;
            int r = idx >> 4, c4 = (idx & 15) * 4;
            int kn = kt*64 + r;
            float4 kv = make_float4(0.f,0.f,0.f,0.f);
            float4 vv = make_float4(0.f,0.f,0.f,0.f);
            if (kn < NTOK) {
                const float* base = qkvb + (size_t)kn*QKVD;
                kv = *(const float4*)(base + 64  + c4);
                vv = *(const float4*)(base + 128 + c4);
            }
            Ks[r*KPITCH + c4+0] = tf32r(kv.x);
            Ks[r*KPITCH + c4+1] = tf32r(kv.y);
            Ks[r*KPITCH + c4+2] = tf32r(kv.z);
            Ks[r*KPITCH + c4+3] = tf32r(kv.w);
            Vs[r*VPITCH + c4+0] = tf32r(vv.x);
            Vs[r*VPITCH + c4+1] = tf32r(vv.y);
            Vs[r*VPITCH + c4+2] = tf32r(vv.z);
            Vs[r*VPITCH + c4+3] = tf32r(vv.w);
        }
        __syncthreads();

        float sf[8][4];
        #pragma unroll
        for (int nt = 0; nt < 8; nt++)
            #pragma unroll
            for (int j = 0; j < 4; j++) sf[nt][j] = 0.f;
        #pragma unroll
        for (int ks = 0; ks < 8; ks++) {
            uint32_t bf[8][2];
            #pragma unroll
            for (int nt = 0; nt < 8; nt++) {
                bf[nt][0] = __float_as_uint(Ks[(nt*8+g)*KPITCH + ks*8 + t    ]);
                bf[nt][1] = __float_as_uint(Ks[(nt*8+g)*KPITCH + ks*8 + t + 4]);
            }
            #pragma unroll
            for (int nt = 0; nt < 8; nt++) {
                asm volatile(
                    "mma.sync.aligned.m16n8k8.row.col.f32.tf32.tf32.f32 "
                    "{%0,%1,%2,%3}, {%4,%5,%6,%7}, {%8,%9}, {%0,%1,%2,%3};"
                    : "+f"(sf[nt][0]), "+f"(sf[nt][1]), "+f"(sf[nt][2]), "+f"(sf[nt][3])
                    : "r"(qf[ks][0]), "r"(qf[ks][1]), "r"(qf[ks][2]), "r"(qf[ks][3]),
                      "r"(bf[nt][0]), "r"(bf[nt][1]));
            }
        }

        float mx0 = -1e30f, mx1 = -1e30f;
        #pragma unroll
        for (int nt = 0; nt < 8; nt++) {
            int c0 = kt*64 + nt*8 + 2*t;
            bool v0 = c0 < NTOK, v1 = (c0+1) < NTOK;
            sf[nt][0] = v0 ? sf[nt][0]*0.125f : -1e30f;
            sf[nt][1] = v1 ? sf[nt][1]*0.125f : -1e30f;
            sf[nt][2] = v0 ? sf[nt][2]*0.125f : -1e30f;
            sf[nt][3] = v1 ? sf[nt][3]*0.125f : -1e30f;
            mx0 = fmaxf(mx0, fmaxf(sf[nt][0], sf[nt][1]));
            mx1 = fmaxf(mx1, fmaxf(sf[nt][2], sf[nt][3]));
        }
        #pragma unroll
        for (int off = 1; off <= 2; off <<= 1) {
            mx0 = fmaxf(mx0, __shfl_xor_sync(0xffffffffu, mx0, off));
            mx1 = fmaxf(mx1, __shfl_xor_sync(0xffffffffu, mx1, off));
        }
        float mn0 = fmaxf(m0, mx0), mn1 = fmaxf(m1, mx1);
        float a0 = __expf(m0 - mn0), a1 = __expf(m1 - mn1);
        m0 = mn0; m1 = mn1;

        float rs0 = 0.f, rs1 = 0.f;
        #pragma unroll
        for (int nt = 0; nt < 8; nt++) {
            sf[nt][0] = __expf(sf[nt][0] - mn0);
            sf[nt][1] = __expf(sf[nt][1] - mn0);
            sf[nt][2] = __expf(sf[nt][2] - mn1);
            sf[nt][3] = __expf(sf[nt][3] - mn1);
            rs0 += sf[nt][0] + sf[nt][1];
            rs1 += sf[nt][2] + sf[nt][3];
        }
        #pragma unroll
        for (int off = 1; off <= 2; off <<= 1) {
            rs0 += __shfl_xor_sync(0xffffffffu, rs0, off);
            rs1 += __shfl_xor_sync(0xffffffffu, rs1, off);
        }
        l0 = l0*a0 + rs0; l1 = l1*a1 + rs1;
        #pragma unroll
        for (int nt = 0; nt < 8; nt++) {
            oacc[nt][0] *= a0; oacc[nt][1] *= a0;
            oacc[nt][2] *= a1; oacc[nt][3] *= a1;
        }

        #pragma unroll
        for (int nt = 0; nt < 8; nt++) {
            Pw[ g   *PPITCH + nt*8 + 2*t    ] = tf32r(sf[nt][0]);
            Pw[ g   *PPITCH + nt*8 + 2*t + 1] = tf32r(sf[nt][1]);
            Pw[(g+8)*PPITCH + nt*8 + 2*t    ] = tf32r(sf[nt][2]);
            Pw[(g+8)*PPITCH + nt*8 + 2*t + 1] = tf32r(sf[nt][3]);
        }
        __syncwarp();

        #pragma unroll
        for (int ks = 0; ks < 8; ks++) {
            uint32_t pf[4];
            pf[0] = __float_as_uint(Pw[ g   *PPITCH + ks*8 + t    ]);
            pf[1] = __float_as_uint(Pw[(g+8)*PPITCH + ks*8 + t    ]);
            pf[2] = __float_as_uint(Pw[ g   *PPITCH + ks*8 + t + 4]);
            pf[3] = __float_as_uint(Pw[(g+8)*PPITCH + ks*8 + t + 4]);
            #pragma unroll
            for (int nt = 0; nt < 8; nt++) {
                uint32_t vf0 = __float_as_uint(Vs[(ks*8 + t    )*VPITCH + nt*8 + g]);
                uint32_t vf1 = __float_as_uint(Vs[(ks*8 + t + 4)*VPITCH + nt*8 + g]);
                asm volatile(
                    "mma.sync.aligned.m16n8k8.row.col.f32.tf32.tf32.f32 "
                    "{%0,%1,%2,%3}, {%4,%5,%6,%7}, {%8,%9}, {%0,%1,%2,%3};"
                    : "+f"(oacc[nt][0]), "+f"(oacc[nt][1]), "+f"(oacc[nt][2]), "+f"(oacc[nt][3])
                    : "r"(pf[0]), "r"(pf[1]), "r"(pf[2]), "r"(pf[3]),
                      "r"(vf0), "r"(vf1));
            }
        }
        __syncwarp();
    }

    float inv0 = 1.0f / l0, inv1 = 1.0f / l1;
    int n0 = qt*64 + warp*16 + g;
    int n1 = n0 + 8;
    #pragma unroll
    for (int nt = 0; nt < 8; nt++) {
        int col = h*64 + nt*8 + 2*t;
        if (n0 < NTOK) {
            float2 v = make_float2(tf32r(oacc[nt][0]*inv0), tf32r(oacc[nt][1]*inv0));
            *(float2*)&o[(size_t)(b*NTOK + n0)*HD + col] = v;
        }
        if (n1 < NTOK) {
            float2 v = make_float2(tf32r(oacc[nt][2]*inv1), tf32r(oacc[nt][3]*inv1));
            *(float2*)&o[(size_t)(b*NTOK + n1)*HD + col] = v;
        }
    }
}

// ---------------- driver ----------------
extern "C" void kernel_launch(void* const* d_in, const int* in_sizes, int n_in,
                              void* d_out, int out_size) {
    const float* x       = (const float*)d_in[0];
    const float* conv_w  = (const float*)d_in[1];
    const float* conv_b  = (const float*)d_in[2];
    const float* cls     = (const float*)d_in[3];
    const float* pos     = (const float*)d_in[4];
    const float* qkv_w   = (const float*)d_in[5];
    const float* merge_w = (const float*)d_in[6];
    const float* merge_b = (const float*)d_in[7];
    const float* ln1_s   = (const float*)d_in[8];
    const float* ln1_b   = (const float*)d_in[9];
    const float* ln2_s   = (const float*)d_in[10];
    const float* ln2_b   = (const float*)d_in[11];
    const float* ffn_w1  = (const float*)d_in[12];
    const float* ffn_b1  = (const float*)d_in[13];
    const float* ffn_w2  = (const float*)d_in[14];
    const float* ffn_b2  = (const float*)d_in[15];
    const float* lnf_s   = (const float*)d_in[16];
    const float* lnf_b   = (const float*)d_in[17];
    float* out = (float*)d_out;

    float *t_p, *h_p, *qkv_p, *o_p, *ffn_p, *patches_p, *tok_p, *wT_p;
    float *wqkv_p, *wmrg_p, *wf1_p, *wf2_p;
    cudaGetSymbolAddress((void**)&t_p,       g_t);
    cudaGetSymbolAddress((void**)&h_p,       g_h);
    cudaGetSymbolAddress((void**)&qkv_p,     g_qkv);
    cudaGetSymbolAddress((void**)&o_p,       g_o);
    cudaGetSymbolAddress((void**)&ffn_p,     g_ffn);
    cudaGetSymbolAddress((void**)&patches_p, g_patches);
    cudaGetSymbolAddress((void**)&tok_p,     g_tok);
    cudaGetSymbolAddress((void**)&wT_p,      g_wT);
    cudaGetSymbolAddress((void**)&wqkv_p,    g_wqkv);
    cudaGetSymbolAddress((void**)&wmrg_p,    g_wmrg);
    cudaGetSymbolAddress((void**)&wf1_p,     g_wf1);
    cudaGetSymbolAddress((void**)&wf2_p,     g_wf2);

    cudaFuncSetAttribute(attn_mma_kernel, cudaFuncAttributeMaxDynamicSharedMemorySize,
                         ATTN_SMEM);
    cudaFuncSetAttribute(gemm_tf32_kernel, cudaFuncAttributeMaxDynamicSharedMemorySize,
                         GEMM_SMEM);

    const int MB = (ROWS + BM - 1) / BM;   // 33

    // pre-round all weights to tf32 (deterministic, rerun every call)
    {
        int n;
        n = DEPTH*DMODEL*QKVD; wround_kernel<<<(n+255)/256, 256>>>(qkv_w,   wqkv_p, n);
        n = DEPTH*HD*DMODEL;   wround_kernel<<<(n+255)/256, 256>>>(merge_w, wmrg_p, n);
        n = DEPTH*DMODEL*MLPD; wround_kernel<<<(n+255)/256, 256>>>(ffn_w1,  wf1_p,  n);
        n = DEPTH*MLPD*DMODEL; wround_kernel<<<(n+255)/256, 256>>>(ffn_w2,  wf2_p,  n);
    }

    // patch embedding
    im2col_kernel<<<4096, 256>>>(x);
    wtrans_kernel<<<768, 256>>>(conv_w);
    gemm_tf32_kernel<<<dim3(DMODEL/BN, 4096/BM), 256, GEMM_SMEM>>>(
        patches_p, wT_p, conv_b, nullptr, tok_p, 4096, 256, DMODEL, 0);
    assemble_kernel<<<(ROWS*DMODEL + 255)/256, 256>>>(cls, pos);

    for (int i = 0; i < DEPTH; i++) {
        ln_kernel<<<ROWS, 256>>>(t_p, ln1_s + i*DMODEL, ln1_b + i*DMODEL, h_p, 1);
        gemm_tf32_kernel<<<dim3(QKVD/BN, MB), 256, GEMM_SMEM>>>(
            h_p, wqkv_p + (size_t)i*DMODEL*QKVD, nullptr, nullptr,
            qkv_p, ROWS, DMODEL, QKVD, 0);
        attn_mma_kernel<<<dim3(17, NHEAD, BATCH), 128, ATTN_SMEM>>>(qkv_p, o_p);
        gemm_tf32_kernel<<<dim3(DMODEL/BN, MB), 256, GEMM_SMEM>>>(
            o_p, wmrg_p + (size_t)i*HD*DMODEL, merge_b + i*DMODEL, t_p,
            t_p, ROWS, HD, DMODEL, 0);
        ln_kernel<<<ROWS, 256>>>(t_p, ln2_s + i*DMODEL, ln2_b + i*DMODEL, h_p, 1);
        gemm_tf32_kernel<<<dim3(MLPD/BN, MB), 256, GEMM_SMEM>>>(
            h_p, wf1_p + (size_t)i*DMODEL*MLPD, ffn_b1 + i*MLPD, nullptr,
            ffn_p, ROWS, DMODEL, MLPD, 1);
        gemm_tf32_kernel<<<dim3(DMODEL/BN, MB), 256, GEMM_SMEM>>>(
            ffn_p, wf2_p + (size_t)i*MLPD*DMODEL, ffn_b2 + i*DMODEL, t_p,
            t_p, ROWS, MLPD, DMODEL, 0);
    }
    ln_kernel<<<ROWS, 256>>>(t_p, lnf_s, lnf_b, out, 0);
}